// round 1
// baseline (speedup 1.0000x reference)
#include <cuda_runtime.h>
#include <math.h>

#define BB 16
#define SS 2048
#define HH 1024

// Scratch (device globals — no allocation allowed)
__device__ float g_u[BB * HH];        // u[b,o] = Wh h[b] + bias
__device__ float g_scores[BB * SS];   // pre-softmax scores

// ---------------------------------------------------------------------------
// Zero scratch + context portion of output (d_out is poisoned each run)
// ---------------------------------------------------------------------------
__global__ void zero_kernel(float* __restrict__ out_ctx) {
    int i = blockIdx.x * blockDim.x + threadIdx.x;
    if (i < BB * SS) g_scores[i] = 0.f;
    if (i < BB * HH) out_ctx[i] = 0.f;
}

// ---------------------------------------------------------------------------
// u[b,o] = sum_h h[b,h] * attn_W[o, h] + bias[o]     (Wh = attn_W[:, :H])
// one warp per (b,o)
// ---------------------------------------------------------------------------
__global__ __launch_bounds__(256) void u_kernel(const float* __restrict__ h,
                                                const float* __restrict__ W,
                                                const float* __restrict__ bias) {
    int gw = (blockIdx.x * blockDim.x + threadIdx.x) >> 5;
    int lane = threadIdx.x & 31;
    if (gw >= BB * HH) return;
    int b = gw >> 10;          // / HH
    int o = gw & (HH - 1);
    const float* hr = h + (size_t)b * HH;
    const float* wr = W + (size_t)o * (2 * HH);   // Wh row
    float acc = 0.f;
#pragma unroll 2
    for (int k = lane * 4; k < HH; k += 32 * 4) {
        float4 hv = *(const float4*)(hr + k);
        float4 wv = *(const float4*)(wr + k);
        acc += hv.x * wv.x + hv.y * wv.y + hv.z * wv.z + hv.w * wv.w;
    }
#pragma unroll
    for (int off = 16; off; off >>= 1)
        acc += __shfl_down_sync(0xffffffffu, acc, off);
    if (lane == 0) g_u[gw] = acc + bias[o];
}

// ---------------------------------------------------------------------------
// Fused GEMM + score epilogue.
//   energy[b,s,o] = a[b,s,:] . Wa[o,:]           (Wa[o,h] = attn_W[o*2H + H + h])
//   scores[b,s] += sum_{o in tile} v[o] * relu(energy + u[b,o])
// Tiles: BM=64 (s) x BN=64 (o) x BK=32 (h), 256 threads, 4x4 microtile.
// ---------------------------------------------------------------------------
#define BM 64
#define BN 64
#define BK 32

__global__ __launch_bounds__(256) void score_kernel(const float* __restrict__ A,
                                                    const float* __restrict__ W,
                                                    const float* __restrict__ v) {
    const int b  = blockIdx.z;
    const int s0 = blockIdx.x * BM;
    const int o0 = blockIdx.y * BN;

    __shared__ float As[BK][BM + 1];   // +1 pad: conflict-free transposed stores
    __shared__ float Ws[BK][BN + 1];
    __shared__ float sp[BM];

    const int tid = threadIdx.x;
    const int lr  = tid >> 3;          // 0..31
    const int lc  = (tid & 7) * 4;     // 0,4,...,28

    const float* Ab = A + ((size_t)b * SS + s0) * HH;
    const float* Wb = W + HH;          // Wa offset within attn_W rows

    const int ty = tid >> 4;           // 0..15 -> s rows ty*4..ty*4+3
    const int tx = tid & 15;           // 0..15 -> o cols tx*4..tx*4+3

    float acc[4][4];
#pragma unroll
    for (int i = 0; i < 4; i++)
#pragma unroll
        for (int j = 0; j < 4; j++) acc[i][j] = 0.f;

    for (int kt = 0; kt < HH; kt += BK) {
#pragma unroll
        for (int rr = 0; rr < BM; rr += 32) {
            float4 av = *(const float4*)(Ab + (size_t)(lr + rr) * HH + kt + lc);
            As[lc + 0][lr + rr] = av.x;
            As[lc + 1][lr + rr] = av.y;
            As[lc + 2][lr + rr] = av.z;
            As[lc + 3][lr + rr] = av.w;
            float4 wv = *(const float4*)(Wb + (size_t)(o0 + lr + rr) * (2 * HH) + kt + lc);
            Ws[lc + 0][lr + rr] = wv.x;
            Ws[lc + 1][lr + rr] = wv.y;
            Ws[lc + 2][lr + rr] = wv.z;
            Ws[lc + 3][lr + rr] = wv.w;
        }
        __syncthreads();
#pragma unroll
        for (int k = 0; k < BK; k++) {
            float af[4], wf[4];
#pragma unroll
            for (int i = 0; i < 4; i++) af[i] = As[k][ty * 4 + i];
#pragma unroll
            for (int j = 0; j < 4; j++) wf[j] = Ws[k][tx * 4 + j];
#pragma unroll
            for (int i = 0; i < 4; i++)
#pragma unroll
                for (int j = 0; j < 4; j++) acc[i][j] += af[i] * wf[j];
        }
        __syncthreads();
    }

    // Epilogue: relu(acc + u) dot v over the o-tile, reduce into scores[b,s]
    if (tid < BM) sp[tid] = 0.f;
    float uv[4], vv[4];
#pragma unroll
    for (int j = 0; j < 4; j++) {
        uv[j] = g_u[b * HH + o0 + tx * 4 + j];
        vv[j] = v[o0 + tx * 4 + j];
    }
    __syncthreads();
#pragma unroll
    for (int i = 0; i < 4; i++) {
        float part = 0.f;
#pragma unroll
        for (int j = 0; j < 4; j++)
            part += vv[j] * fmaxf(acc[i][j] + uv[j], 0.f);
        atomicAdd(&sp[ty * 4 + i], part);
    }
    __syncthreads();
    if (tid < BM) atomicAdd(&g_scores[b * SS + s0 + tid], sp[tid]);
}

// ---------------------------------------------------------------------------
// Softmax over S per batch row; writes attn_weights to output.
// ---------------------------------------------------------------------------
__global__ __launch_bounds__(256) void softmax_kernel(float* __restrict__ wout) {
    const int b = blockIdx.x;
    const int tid = threadIdx.x;
    __shared__ float red[256];

    float vls[8];
    float m = -1e30f;
#pragma unroll
    for (int i = 0; i < 8; i++) {
        vls[i] = g_scores[b * SS + i * 256 + tid];
        m = fmaxf(m, vls[i]);
    }
    red[tid] = m; __syncthreads();
    for (int off = 128; off; off >>= 1) {
        if (tid < off) red[tid] = fmaxf(red[tid], red[tid + off]);
        __syncthreads();
    }
    m = red[0]; __syncthreads();

    float s = 0.f;
#pragma unroll
    for (int i = 0; i < 8; i++) {
        vls[i] = expf(vls[i] - m);
        s += vls[i];
    }
    red[tid] = s; __syncthreads();
    for (int off = 128; off; off >>= 1) {
        if (tid < off) red[tid] += red[tid + off];
        __syncthreads();
    }
    float inv = 1.f / red[0];
#pragma unroll
    for (int i = 0; i < 8; i++)
        wout[b * SS + i * 256 + tid] = vls[i] * inv;
}

// ---------------------------------------------------------------------------
// context[b,h] = sum_s w[b,s] * a[b,s,h]   (S split 4 ways, atomicAdd)
// ---------------------------------------------------------------------------
#define SSPLIT 4
#define SCHUNK (SS / SSPLIT)

__global__ __launch_bounds__(256) void context_kernel(const float* __restrict__ A,
                                                      const float* __restrict__ wts,
                                                      float* __restrict__ out_ctx) {
    const int b = blockIdx.y;
    const int hI = blockIdx.x * 256 + threadIdx.x;
    const int s_base = blockIdx.z * SCHUNK;

    __shared__ float ws[SCHUNK];
    for (int i = threadIdx.x; i < SCHUNK; i += 256)
        ws[i] = wts[b * SS + s_base + i];
    __syncthreads();

    const float* Ab = A + ((size_t)b * SS + s_base) * HH + hI;
    float a0 = 0.f, a1 = 0.f, a2 = 0.f, a3 = 0.f;
#pragma unroll 1
    for (int s = 0; s < SCHUNK; s += 4) {
        a0 += ws[s + 0] * Ab[(size_t)(s + 0) * HH];
        a1 += ws[s + 1] * Ab[(size_t)(s + 1) * HH];
        a2 += ws[s + 2] * Ab[(size_t)(s + 2) * HH];
        a3 += ws[s + 3] * Ab[(size_t)(s + 3) * HH];
    }
    atomicAdd(&out_ctx[b * HH + hI], (a0 + a1) + (a2 + a3));
}

// ---------------------------------------------------------------------------
// Launch
// Inputs (metadata order): h, c(unused), encoder_outputs, attn_W, attn_b, v_W
// Output: [context (B*H floats) | attn_weights (B*S floats)]
// ---------------------------------------------------------------------------
extern "C" void kernel_launch(void* const* d_in, const int* in_sizes, int n_in,
                              void* d_out, int out_size) {
    const float* h    = (const float*)d_in[0];
    const float* enc  = (const float*)d_in[2];
    const float* W    = (const float*)d_in[3];
    const float* bias = (const float*)d_in[4];
    const float* vW   = (const float*)d_in[5];
    float* out     = (float*)d_out;
    float* out_ctx = out;               // B*H context
    float* out_w   = out + BB * HH;     // B*S attention weights

    zero_kernel<<<(BB * SS + 255) / 256, 256>>>(out_ctx);
    u_kernel<<<(BB * HH * 32) / 256, 256>>>(h, W, bias);
    dim3 g(SS / BM, HH / BN, BB);
    score_kernel<<<g, 256>>>(enc, W, vW);
    softmax_kernel<<<BB, 256>>>(out_w);
    dim3 gc(HH / 256, BB, SSPLIT);
    context_kernel<<<gc, 256>>>(enc, out_w, out_ctx);
}

// round 3
// speedup vs baseline: 4.6892x; 4.6892x over previous
#include <cuda_runtime.h>
#include <cuda_fp16.h>
#include <cstdint>
#include <math.h>

#define BB 16
#define SS 2048
#define HH 1024

// ---------------- scratch ----------------
__device__ float g_u[BB * HH];
__device__ float g_scores[BB * SS];

__device__ __forceinline__ uint32_t smem_u32(const void* p) {
    uint32_t a;
    asm("{ .reg .u64 t; cvta.to.shared.u64 t, %1; cvt.u32.u64 %0, t; }" : "=r"(a) : "l"(p));
    return a;
}
__device__ __forceinline__ void ldsm4(uint32_t* d, uint32_t addr) {
    asm volatile("ldmatrix.sync.aligned.m8n8.x4.shared.b16 {%0,%1,%2,%3}, [%4];"
                 : "=r"(d[0]), "=r"(d[1]), "=r"(d[2]), "=r"(d[3]) : "r"(addr));
}
__device__ __forceinline__ void mma16816(float* d, const uint32_t* a, const uint32_t* b) {
    asm volatile(
        "mma.sync.aligned.m16n8k16.row.col.f32.f16.f16.f32 "
        "{%0,%1,%2,%3},{%4,%5,%6,%7},{%8,%9},{%0,%1,%2,%3};"
        : "+f"(d[0]), "+f"(d[1]), "+f"(d[2]), "+f"(d[3])
        : "r"(a[0]), "r"(a[1]), "r"(a[2]), "r"(a[3]), "r"(b[0]), "r"(b[1]));
}

// ---------------------------------------------------------------------------
__global__ void zero_kernel(float* __restrict__ out_ctx) {
    int i = blockIdx.x * blockDim.x + threadIdx.x;
    if (i < BB * SS) g_scores[i] = 0.f;
    if (i < BB * HH) out_ctx[i] = 0.f;
}

// u[b,o] = Wh h[b] + bias
__global__ __launch_bounds__(256) void u_kernel(const float* __restrict__ h,
                                                const float* __restrict__ W,
                                                const float* __restrict__ bias) {
    int gw = (blockIdx.x * blockDim.x + threadIdx.x) >> 5;
    int lane = threadIdx.x & 31;
    if (gw >= BB * HH) return;
    int b = gw >> 10;
    int o = gw & (HH - 1);
    const float* hr = h + (size_t)b * HH;
    const float* wr = W + (size_t)o * (2 * HH);
    float acc = 0.f;
#pragma unroll 2
    for (int k = lane * 4; k < HH; k += 32 * 4) {
        float4 hv = *(const float4*)(hr + k);
        float4 wv = *(const float4*)(wr + k);
        acc += hv.x * wv.x + hv.y * wv.y + hv.z * wv.z + hv.w * wv.w;
    }
#pragma unroll
    for (int off = 16; off; off >>= 1) acc += __shfl_down_sync(0xffffffffu, acc, off);
    if (lane == 0) g_u[gw] = acc + bias[o];
}

// ---------------------------------------------------------------------------
// Fused score GEMM via mma.sync fp16 (fp32 accumulate).
//   D[s,o] = A[s,:] . Wa[o,:],   scores[b,s] += sum_o v[o]*relu(D + u[b,o])
// BM=128, BN=128, BK=32(fp32 elems), 256 threads, warps 4(M)x2(N), warp 32x64.
// smem: fp16 tiles, 128B physical rows (2 logical 64B rows), XOR-16B-chunk swizzle.
// ---------------------------------------------------------------------------
#define BM 128
#define BN 128
#define BKF 32
#define NTILE (HH / BKF)

__global__ __launch_bounds__(256) void score_kernel(const float* __restrict__ A,
                                                    const float* __restrict__ W,
                                                    const float* __restrict__ v) {
    __shared__ __align__(16) uint8_t sA[2][8192];
    __shared__ __align__(16) uint8_t sW[2][8192];
    __shared__ float u_s[BN], v_s[BN], sp[BM];

    const int tid = threadIdx.x;
    const int wid = tid >> 5;
    const int lane = tid & 31;
    const int g = lane >> 2;
    const int tg = lane & 3;
    const int warpM0 = (wid & 3) * 32;
    const int warpN0 = (wid >> 2) * 64;

    const int o0 = blockIdx.x * BN;
    const int bs0 = blockIdx.y * BM;
    const int b = bs0 >> 11;               // / SS

    if (tid < BN) { u_s[tid] = g_u[b * HH + o0 + tid]; v_s[tid] = v[o0 + tid]; }
    if (tid < BM) sp[tid] = 0.f;

    // loader mapping: row lr (0..127), chunk pair cp (0 or 2); chunk = 8 halfs (16B)
    const int lr = tid >> 1;
    const int cp = (tid & 1) * 2;
    const float* Arow = A + (size_t)(bs0 + lr) * HH + cp * 8;
    const float* Wrow = W + (size_t)(o0 + lr) * (2 * HH) + HH + cp * 8;

    const uint32_t sAb0 = smem_u32(sA[0]);
    const uint32_t sAb1 = smem_u32(sA[1]);
    const uint32_t sWb0 = smem_u32(sW[0]);
    const uint32_t sWb1 = smem_u32(sW[1]);

    float4 pf[8];

    auto ldg_tile = [&](int t) {
        const float* a = Arow + t * BKF;
        const float* w = Wrow + t * BKF;
        pf[0] = *(const float4*)(a + 0);
        pf[1] = *(const float4*)(a + 4);
        pf[2] = *(const float4*)(a + 8);
        pf[3] = *(const float4*)(a + 12);
        pf[4] = *(const float4*)(w + 0);
        pf[5] = *(const float4*)(w + 4);
        pf[6] = *(const float4*)(w + 8);
        pf[7] = *(const float4*)(w + 12);
    };

    const int prow_st = lr >> 1;
    auto sts_tile = [&](int stage) {
        uint8_t* baseA = sA[stage];
        uint8_t* baseW = sW[stage];
#pragma unroll
        for (int j = 0; j < 2; j++) {
            int c = cp + j;
            int swz = (((lr & 1) * 4 + c) ^ (prow_st & 7));
            uint32_t off = (uint32_t)(prow_st * 128 + swz * 16);
            {
                float4 x = pf[j * 2], y = pf[j * 2 + 1];
                __half2 h0 = __floats2half2_rn(x.x, x.y);
                __half2 h1 = __floats2half2_rn(x.z, x.w);
                __half2 h2 = __floats2half2_rn(y.x, y.y);
                __half2 h3 = __floats2half2_rn(y.z, y.w);
                uint4 val = make_uint4(*(uint32_t*)&h0, *(uint32_t*)&h1,
                                       *(uint32_t*)&h2, *(uint32_t*)&h3);
                *(uint4*)(baseA + off) = val;
            }
            {
                float4 x = pf[4 + j * 2], y = pf[4 + j * 2 + 1];
                __half2 h0 = __floats2half2_rn(x.x, x.y);
                __half2 h1 = __floats2half2_rn(x.z, x.w);
                __half2 h2 = __floats2half2_rn(y.x, y.y);
                __half2 h3 = __floats2half2_rn(y.z, y.w);
                uint4 val = make_uint4(*(uint32_t*)&h0, *(uint32_t*)&h1,
                                       *(uint32_t*)&h2, *(uint32_t*)&h3);
                *(uint4*)(baseW + off) = val;
            }
        }
    };

    float acc[2][8][4];
#pragma unroll
    for (int mb = 0; mb < 2; mb++)
#pragma unroll
        for (int nb = 0; nb < 8; nb++)
#pragma unroll
            for (int r = 0; r < 4; r++) acc[mb][nb][r] = 0.f;

    // precompute LDSM lane address offsets (stage-relative)
    uint32_t a_off[2][2], b_off[2][4];   // [ks][mb] / [ks][npair]
#pragma unroll
    for (int ks = 0; ks < 2; ks++) {
#pragma unroll
        for (int mb = 0; mb < 2; mb++) {
            int mrow = warpM0 + mb * 16 + (lane & 7) + ((lane >> 3) & 1) * 8;
            int ch = ks * 2 + ((lane >> 4) & 1);
            int prow = mrow >> 1;
            int swz = (((mrow & 1) * 4 + ch) ^ (prow & 7));
            a_off[ks][mb] = (uint32_t)(prow * 128 + swz * 16);
        }
#pragma unroll
        for (int np = 0; np < 4; np++) {
            int nrow = warpN0 + np * 16 + (lane & 7) + ((lane >> 4) & 1) * 8;
            int ch = ks * 2 + ((lane >> 3) & 1);
            int prow = nrow >> 1;
            int swz = (((nrow & 1) * 4 + ch) ^ (prow & 7));
            b_off[ks][np] = (uint32_t)(prow * 128 + swz * 16);
        }
    }

    auto mma_stage = [&](int stage) {
        const uint32_t baseA = stage ? sAb1 : sAb0;
        const uint32_t baseW = stage ? sWb1 : sWb0;
#pragma unroll
        for (int ks = 0; ks < 2; ks++) {
            uint32_t af[2][4];
            uint32_t bf[4][4];
            ldsm4(af[0], baseA + a_off[ks][0]);
            ldsm4(af[1], baseA + a_off[ks][1]);
#pragma unroll
            for (int np = 0; np < 4; np++) ldsm4(bf[np], baseW + b_off[ks][np]);
#pragma unroll
            for (int mb = 0; mb < 2; mb++)
#pragma unroll
                for (int nb = 0; nb < 8; nb++)
                    mma16816(acc[mb][nb], af[mb], &bf[nb >> 1][(nb & 1) * 2]);
        }
    };

    ldg_tile(0);
    sts_tile(0);
    __syncthreads();

#pragma unroll 1
    for (int t = 0; t < NTILE; t++) {
        if (t + 1 < NTILE) ldg_tile(t + 1);
        mma_stage(t & 1);
        if (t + 1 < NTILE) sts_tile((t + 1) & 1);
        __syncthreads();
    }

    // ---- epilogue: score[s] += sum_o v[o]*relu(acc + u[b,o]) ----
    float p[2][2] = {{0.f, 0.f}, {0.f, 0.f}};
#pragma unroll
    for (int mb = 0; mb < 2; mb++)
#pragma unroll
        for (int nb = 0; nb < 8; nb++)
#pragma unroll
            for (int r = 0; r < 4; r++) {
                int n = warpN0 + nb * 8 + 2 * tg + (r & 1);
                float e = acc[mb][nb][r] + u_s[n];
                p[mb][r >> 1] += v_s[n] * fmaxf(e, 0.f);
            }
#pragma unroll
    for (int mb = 0; mb < 2; mb++)
#pragma unroll
        for (int hf = 0; hf < 2; hf++) {
            float x = p[mb][hf];
            x += __shfl_xor_sync(0xffffffffu, x, 1);
            x += __shfl_xor_sync(0xffffffffu, x, 2);
            if (tg == 0) atomicAdd(&sp[warpM0 + mb * 16 + hf * 8 + g], x);
        }
    __syncthreads();
    if (tid < BM) atomicAdd(&g_scores[bs0 + tid], sp[tid]);
}

// ---------------------------------------------------------------------------
__global__ __launch_bounds__(256) void softmax_kernel(float* __restrict__ wout) {
    const int b = blockIdx.x;
    const int tid = threadIdx.x;
    __shared__ float red[256];

    float vls[8];
    float m = -1e30f;
#pragma unroll
    for (int i = 0; i < 8; i++) {
        vls[i] = g_scores[b * SS + i * 256 + tid];
        m = fmaxf(m, vls[i]);
    }
    red[tid] = m; __syncthreads();
    for (int off = 128; off; off >>= 1) {
        if (tid < off) red[tid] = fmaxf(red[tid], red[tid + off]);
        __syncthreads();
    }
    m = red[0]; __syncthreads();

    float s = 0.f;
#pragma unroll
    for (int i = 0; i < 8; i++) { vls[i] = expf(vls[i] - m); s += vls[i]; }
    red[tid] = s; __syncthreads();
    for (int off = 128; off; off >>= 1) {
        if (tid < off) red[tid] += red[tid + off];
        __syncthreads();
    }
    float inv = 1.f / red[0];
#pragma unroll
    for (int i = 0; i < 8; i++)
        wout[b * SS + i * 256 + tid] = vls[i] * inv;
}

// ---------------------------------------------------------------------------
#define SSPLIT 4
#define SCHUNK (SS / SSPLIT)

__global__ __launch_bounds__(256) void context_kernel(const float* __restrict__ A,
                                                      const float* __restrict__ wts,
                                                      float* __restrict__ out_ctx) {
    const int b = blockIdx.y;
    const int hI = blockIdx.x * 256 + threadIdx.x;
    const int s_base = blockIdx.z * SCHUNK;

    __shared__ float ws[SCHUNK];
    for (int i = threadIdx.x; i < SCHUNK; i += 256)
        ws[i] = wts[b * SS + s_base + i];
    __syncthreads();

    const float* Ab = A + ((size_t)b * SS + s_base) * HH + hI;
    float a0 = 0.f, a1 = 0.f, a2 = 0.f, a3 = 0.f;
#pragma unroll 1
    for (int s = 0; s < SCHUNK; s += 4) {
        a0 += ws[s + 0] * Ab[(size_t)(s + 0) * HH];
        a1 += ws[s + 1] * Ab[(size_t)(s + 1) * HH];
        a2 += ws[s + 2] * Ab[(size_t)(s + 2) * HH];
        a3 += ws[s + 3] * Ab[(size_t)(s + 3) * HH];
    }
    atomicAdd(&out_ctx[b * HH + hI], (a0 + a1) + (a2 + a3));
}

// ---------------------------------------------------------------------------
extern "C" void kernel_launch(void* const* d_in, const int* in_sizes, int n_in,
                              void* d_out, int out_size) {
    const float* h = (const float*)d_in[0];
    const float* enc = (const float*)d_in[2];
    const float* W = (const float*)d_in[3];
    const float* bias = (const float*)d_in[4];
    const float* vW = (const float*)d_in[5];
    float* out = (float*)d_out;
    float* out_ctx = out;
    float* out_w = out + BB * HH;

    zero_kernel<<<(BB * SS + 255) / 256, 256>>>(out_ctx);
    u_kernel<<<(BB * HH * 32) / 256, 256>>>(h, W, bias);
    dim3 g(HH / BN, (BB * SS) / BM);
    score_kernel<<<g, 256>>>(enc, W, vW);
    softmax_kernel<<<BB, 256>>>(out_w);
    dim3 gc(HH / 256, BB, SSPLIT);
    context_kernel<<<gc, 256>>>(enc, out_w, out_ctx);
}